// round 9
// baseline (speedup 1.0000x reference)
#include <cuda_runtime.h>
#include <cuda_fp16.h>

#define BB   256
#define NN   1152
#define OO   10
#define JJ   160              // floats per (b,n): j = o*16+k
#define WW   80               // half2 words per (b,n)
#define EPSF 1e-7f
#define NPART 18
#define NPERW 16              // n per warp: 1152/(NPART*4)

typedef unsigned long long ull;

// ---- scratch (static device globals; no allocation) ----
__device__ __half2 g_uh[(size_t)BB * NN * WW];     // 94.5 MB, [b][n][w]
__device__ float   g_part[36 * BB * JJ];           // 5.9 MB uhat partials
__device__ float   g_s0[BB * JJ];
__device__ float   g_sA[BB * JJ];
__device__ float   g_sB[BB * JJ];

// ---- packed f32x2 helpers ----
__device__ __forceinline__ ull fma2(ull a, ull b, ull c) {
    ull d; asm("fma.rn.f32x2 %0, %1, %2, %3;" : "=l"(d) : "l"(a), "l"(b), "l"(c));
    return d;
}
__device__ __forceinline__ ull add2(ull a, ull b) {
    ull d; asm("add.rn.f32x2 %0, %1, %2;" : "=l"(d) : "l"(a), "l"(b));
    return d;
}
__device__ __forceinline__ ull pack2(float lo, float hi) {
    ull d; asm("mov.b64 %0, {%1, %2};" : "=l"(d) : "f"(lo), "f"(hi));
    return d;
}
__device__ __forceinline__ float2 unpack2(ull v) {
    float lo, hi; asm("mov.b64 {%0, %1}, %2;" : "=f"(lo), "=f"(hi) : "l"(v));
    return make_float2(lo, hi);
}

// ---------------------------------------------------------------------------
__global__ void k_zero() {
    int i = blockIdx.x * blockDim.x + threadIdx.x;
    if (i < BB * JJ) { g_s0[i] = 0.f; g_sA[i] = 0.f; g_sB[i] = 0.f; }
}

// ---------------------------------------------------------------------------
// u_hat via packed f32x2 FMA, 32 n per block (4 chunks of 8 n-pairs).
// grid (36, 8), block 160 (thread = j).  s0 partials kept in smem across chunks.
__global__ void __launch_bounds__(160) k_uhat(const float* __restrict__ x,
                                              const float* __restrict__ w) {
    const int j  = threadIdx.x;
    const int n0 = blockIdx.x * 32;
    const int b0 = blockIdx.y * 32;

    __shared__ __align__(16) float x_sm[32 * 64];   // [bb][i*8+n]
    __shared__ float acc_sm[32][JJ];                // s0 partials per bb

    for (int idx = j; idx < 32 * JJ; idx += 160) ((float*)acc_sm)[idx] = 0.f;

    const int wb = (j >> 4) * 128 + (j & 15);       // o*128 + k
    __half* gh = (__half*)g_uh;
    const ull z2 = pack2(0.f, 0.f);

    for (int c = 0; c < 4; c++) {
        const int n0c = n0 + c * 8;
        __syncthreads();                            // protect x_sm reuse
        for (int idx = j; idx < 32 * 64; idx += 160) {
            int bb = idx >> 6, q = idx & 63;        // q = n*8+i
            int n = q >> 3, i = q & 7;
            x_sm[bb * 64 + i * 8 + n] =
                x[(size_t)(b0 + bb) * (NN * 8) + (n0c + n) * 8 + i];
        }
        ull Wp[4][8];
        #pragma unroll
        for (int p = 0; p < 4; p++)
            #pragma unroll
            for (int i = 0; i < 8; i++) {
                float a = w[(size_t)(n0c + 2 * p)     * 1280 + wb + i * 16];
                float b = w[(size_t)(n0c + 2 * p + 1) * 1280 + wb + i * 16];
                Wp[p][i] = pack2(a, b);
            }
        __syncthreads();

        for (int bb = 0; bb < 32; bb++) {
            ull s2 = z2;
            __half* outp = &gh[((size_t)(b0 + bb) * NN + n0c) * JJ + j];
            const ull* xrow = (const ull*)&x_sm[bb * 64];
            #pragma unroll
            for (int p = 0; p < 4; p++) {
                ull acc = z2;
                #pragma unroll
                for (int i = 0; i < 8; i++)
                    acc = fma2(Wp[p][i], xrow[i * 4 + p], acc);
                s2 = add2(s2, acc);
                float2 u = unpack2(acc);
                outp[(2 * p)     * JJ] = __float2half(u.x);
                outp[(2 * p + 1) * JJ] = __float2half(u.y);
            }
            float2 sf = unpack2(s2);
            acc_sm[bb][j] += sf.x + sf.y;
        }
    }
    __syncthreads();
    for (int bb = 0; bb < 32; bb++)
        g_part[((size_t)blockIdx.x * BB + (b0 + bb)) * JJ + j] = acc_sm[bb][j];
}

// ---------------------------------------------------------------------------
__global__ void k_red0() {
    const int b = blockIdx.x, j = threadIdx.x;
    const int nb0 = blockIdx.y * 9;
    float s = 0.f;
    #pragma unroll 3
    for (int nb = nb0; nb < nb0 + 9; nb++)
        s += g_part[((size_t)nb * BB + b) * JJ + j];
    atomicAdd(&g_s0[b * JJ + j], s);
}

// ---------------------------------------------------------------------------
__global__ void k_squash(const float* __restrict__ sbuf, float scale,
                         const float* __restrict__ bias, float* __restrict__ dst) {
    const int b = blockIdx.x, j = threadIdx.x;
    float s = scale * sbuf[b * JJ + j] + bias[j];
    float d = s * s;
    #pragma unroll
    for (int msk = 1; msk < 16; msk <<= 1)
        d += __shfl_xor_sync(0xffffffffu, d, msk, 16);
    dst[b * JJ + j] = s * (d / ((1.f + d) * sqrtf(d + EPSF)));
}

// ---------------------------------------------------------------------------
__device__ __forceinline__ float squash1(float s) {
    float d = s * s;
    #pragma unroll
    for (int msk = 1; msk < 16; msk <<= 1)
        d += __shfl_xor_sync(0xffffffffu, d, msk, 16);
    return s * (d / ((1.f + d) * sqrtf(d + EPSF)));
}

// ---------------------------------------------------------------------------
// Routing iteration, 2-n-per-warp-step, b1-free, 2-pair groups, <=64 regs.
// grid (256 b, NPART), block 128 (4 warps, NPERW=16 n = 8 pairs each).
// Lane l<20: parity = l&1 (n vs n+1), o = l>>1; lane-local 16-k dot, 4-shfl softmax.
template <int ITER>
__global__ void __launch_bounds__(128, 8) k_route(const float* __restrict__ s0in,
                                                  const float* __restrict__ sAin,
                                                  const float* __restrict__ bias,
                                                  float* __restrict__ sout) {
    const int b   = blockIdx.x;
    const int tid = threadIdx.x;
    const int wp  = tid >> 5, l = tid & 31;
    const unsigned FULL = 0xffffffffu;
    const bool act = (l < 20);

    __shared__ __align__(16) float vsum_sm[JJ];
    {
        float v = squash1(0.1f * s0in[b * JJ + tid] + bias[tid]);
        if (ITER == 2) v += squash1(sAin[b * JJ + tid] + bias[tid]);
        vsum_sm[tid] = v;
        if (tid < 32) {
            int j2 = 128 + tid;
            float v2 = squash1(0.1f * s0in[b * JJ + j2] + bias[j2]);
            if (ITER == 2) v2 += squash1(sAin[b * JJ + j2] + bias[j2]);
            vsum_sm[j2] = v2;
        }
    }
    __syncthreads();

    float vreg[16];
    {
        const int o = l >> 1;
        const float4* vp = (const float4*)&vsum_sm[(act ? o : 0) * 16];
        #pragma unroll
        for (int q = 0; q < 4; q++) {
            float4 t = vp[q];
            vreg[4 * q] = t.x; vreg[4 * q + 1] = t.y;
            vreg[4 * q + 2] = t.z; vreg[4 * q + 3] = t.w;
        }
    }

    float sacc[16];
    #pragma unroll
    for (int k = 0; k < 16; k++) sacc[k] = 0.f;

    const int nbeg = (blockIdx.y * 4 + wp) * NPERW;
    const char* ub = (const char*)g_uh + ((size_t)b * NN + nbeg) * 320
                   + (l & 1) * 320 + (l >> 1) * 32;

    for (int g = 0; g < 4; g++) {                    // 4 groups of 2 pairs
        float4 A[2], Bq[2];
        #pragma unroll
        for (int p = 0; p < 2; p++) {
            const char* ap = ub + (g * 2 + p) * 640;
            A[p]  = act ? *(const float4*)ap        : make_float4(0.f, 0.f, 0.f, 0.f);
            Bq[p] = act ? *(const float4*)(ap + 16) : make_float4(0.f, 0.f, 0.f, 0.f);
        }
        #pragma unroll
        for (int p = 0; p < 2; p++) {
            const __half2* h2a = (const __half2*)&A[p];
            const __half2* h2b = (const __half2*)&Bq[p];
            float acc = 0.f;
            #pragma unroll
            for (int i = 0; i < 4; i++) {
                float2 t = __half22float2(h2a[i]);
                acc = fmaf(t.x, vreg[2 * i], fmaf(t.y, vreg[2 * i + 1], acc));
            }
            #pragma unroll
            for (int i = 0; i < 4; i++) {
                float2 t = __half22float2(h2b[i]);
                acc = fmaf(t.x, vreg[8 + 2 * i], fmaf(t.y, vreg[8 + 2 * i + 1], acc));
            }
            float e = act ? __expf(acc) : 0.f;
            float tot = e;                           // Σ over same-parity lanes
            tot += __shfl_xor_sync(FULL, tot, 2);
            tot += __shfl_xor_sync(FULL, tot, 4);
            tot += __shfl_xor_sync(FULL, tot, 8);
            tot += __shfl_xor_sync(FULL, tot, 16);
            float c = __fdividef(e, tot);
            #pragma unroll
            for (int i = 0; i < 4; i++) {
                float2 t = __half22float2(h2a[i]);
                sacc[2 * i]     = fmaf(c, t.x, sacc[2 * i]);
                sacc[2 * i + 1] = fmaf(c, t.y, sacc[2 * i + 1]);
            }
            #pragma unroll
            for (int i = 0; i < 4; i++) {
                float2 t = __half22float2(h2b[i]);
                sacc[8 + 2 * i]     = fmaf(c, t.x, sacc[8 + 2 * i]);
                sacc[8 + 2 * i + 1] = fmaf(c, t.y, sacc[8 + 2 * i + 1]);
            }
        }
    }

    __shared__ __align__(16) float ssm[4][2][JJ];
    if (act) {
        float4* sp = (float4*)&ssm[wp][l & 1][(l >> 1) * 16];
        #pragma unroll
        for (int q = 0; q < 4; q++)
            sp[q] = make_float4(sacc[4 * q], sacc[4 * q + 1],
                                sacc[4 * q + 2], sacc[4 * q + 3]);
    }
    __syncthreads();

    for (int jj = tid; jj < JJ; jj += 128) {
        float s = 0.f;
        #pragma unroll
        for (int w4 = 0; w4 < 4; w4++)
            s += ssm[w4][0][jj] + ssm[w4][1][jj];
        atomicAdd(&sout[b * JJ + jj], s);
    }
}

// ---------------------------------------------------------------------------
extern "C" void kernel_launch(void* const* d_in, const int* in_sizes, int n_in,
                              void* d_out, int out_size) {
    const float* x    = (const float*)d_in[0];
    const float* w    = (const float*)d_in[1];
    const float* bias = (const float*)d_in[2];
    float* out = (float*)d_out;

    float* s0; cudaGetSymbolAddress((void**)&s0, g_s0);
    float* sA; cudaGetSymbolAddress((void**)&sA, g_sA);
    float* sB; cudaGetSymbolAddress((void**)&sB, g_sB);

    k_zero<<<40, 1024>>>();
    k_uhat<<<dim3(36, 8), 160>>>(x, w);
    k_red0<<<dim3(256, 4), 160>>>();
    k_route<1><<<dim3(256, NPART), 128>>>(s0, nullptr, bias, sA);  // iter 1
    k_route<2><<<dim3(256, NPART), 128>>>(s0, sA, bias, sB);       // iter 2
    k_squash<<<256, 160>>>(sB, 1.0f, bias, out);                   // final
}